// round 8
// baseline (speedup 1.0000x reference)
#include <cuda_runtime.h>
#include <cstdint>
#include <math.h>

// Problem constants
#define T_SEQ 2048
#define H     256
#define G3    768          // 3*H gate rows
#define VOUT  32000

// Scan cluster config
#define CLN          8     // cluster size
#define SLICE        32    // hidden units per CTA (H / CLN)
#define ROWS_PER_CTA 96    // 3 * SLICE rows of W_hh per CTA
#define WPITCH       272   // padded row pitch (floats) -> conflict-free LDS.128
#define SCAN_THREADS 384   // 96 row-teams * 4 lanes

// ---------------------------------------------------------------------------
// Device scratch (static __device__ arrays: allocation-free per harness rules)
// ---------------------------------------------------------------------------
__device__ __align__(16) float g_Xenc[T_SEQ * H];
__device__ __align__(16) float g_Xdec[T_SEQ * H];
__device__ __align__(16) float g_gi_enc[T_SEQ * G3];
__device__ __align__(16) float g_gi_dec[T_SEQ * G3];
__device__ __align__(16) float g_Hs[T_SEQ * H];
__device__ __align__(16) float g_sumexp[T_SEQ];

// ---------------------------------------------------------------------------
// PTX helpers
// ---------------------------------------------------------------------------
__device__ __forceinline__ uint32_t cvta_smem(const void* p) {
    return (uint32_t)__cvta_generic_to_shared(p);
}
__device__ __forceinline__ uint32_t mapa_u32(uint32_t laddr, uint32_t rank) {
    uint32_t r;
    asm("mapa.shared::cluster.u32 %0, %1, %2;" : "=r"(r) : "r"(laddr), "r"(rank));
    return r;
}
__device__ __forceinline__ void mbar_init(uint32_t addr, uint32_t count) {
    asm volatile("mbarrier.init.shared.b64 [%0], %1;" :: "r"(addr), "r"(count) : "memory");
}
// remote (or local) arrive with cluster-scope release: seals this thread's
// prior st.shared::cluster stores for any acquirer of this barrier.
__device__ __forceinline__ void mbar_arrive_cluster(uint32_t addr) {
    asm volatile("mbarrier.arrive.release.cluster.shared::cluster.b64 _, [%0];"
                 :: "r"(addr) : "memory");
}
// local wait with cluster-scope acquire (sees peers' DSMEM stores)
__device__ __forceinline__ void mbar_wait_cluster(uint32_t addr, uint32_t parity) {
    asm volatile(
        "{\n\t.reg .pred P;\n\t"
        "WL_%=:\n\t"
        "mbarrier.try_wait.parity.acquire.cluster.shared::cta.b64 P, [%0], %1, 0x989680;\n\t"
        "@!P bra WL_%=;\n\t"
        "}" :: "r"(addr), "r"(parity) : "memory");
}
#define CLUSTER_SYNC_() do { \
    asm volatile("barrier.cluster.arrive.aligned;" ::: "memory"); \
    asm volatile("barrier.cluster.wait.aligned;"   ::: "memory"); \
} while (0)

// ---------------------------------------------------------------------------
// 1) Gather embeddings (+ relu for decoder input) and zero the sum-exp accum.
// ---------------------------------------------------------------------------
__global__ void gather_kernel(const int* __restrict__ src, const int* __restrict__ trg,
                              const float* __restrict__ enc_emb,
                              const float* __restrict__ dec_emb)
{
    int t = blockIdx.x;
    int i = threadIdx.x;           // 256 threads
    int s = src[t];
    int d = trg[t];
    g_Xenc[t * H + i] = enc_emb[(size_t)s * H + i];
    float v = dec_emb[(size_t)d * H + i];
    g_Xdec[t * H + i] = v > 0.f ? v : 0.f;
    if (t < T_SEQ / H) g_sumexp[t * H + i] = 0.f;   // 8 blocks zero all 2048 entries
}

// ---------------------------------------------------------------------------
// 2) fp32 GEMM: C[M][N] = A[M][256] * B[N][256]^T + bias[N]
//    128x128 tiles, BK=16, 256 threads, 8x8 micro-tile -> ~90%+ FFMA-pipe.
//    do_lse: accumulate per-row sum(exp(c)) into g_sumexp (logits GEMM only).
//    Requires M % 128 == 0 and N % 128 == 0 (2048 / 768 / 32000 qualify).
// ---------------------------------------------------------------------------
__global__ __launch_bounds__(256)
void gemm_kernel(const float* __restrict__ A, const float* __restrict__ B,
                 const float* __restrict__ bias, float* __restrict__ C,
                 int N, int do_lse)
{
    __shared__ float As[16][132];   // [k][m], padded
    __shared__ float Bs[16][132];   // [k][n], padded

    int tid = threadIdx.x;
    int tx = tid & 15;              // 0..15 : col group (8 cols)
    int ty = tid >> 4;              // 0..15 : row group (8 rows)
    int bm = blockIdx.x * 128;
    int bn = blockIdx.y * 128;

    int lr  = tid >> 1;             // 0..127 : tile row for loads
    int lk8 = (tid & 1) * 8;        // 0 or 8 : k offset for loads

    const float* Ap = A + (size_t)(bm + lr) * 256 + lk8;
    const float* Bp = B + (size_t)(bn + lr) * 256 + lk8;

    float acc[8][8] = {};

    // prefetch first k-block into regs
    float4 ra0 = *(const float4*)(Ap + 0);
    float4 ra1 = *(const float4*)(Ap + 4);
    float4 rb0 = *(const float4*)(Bp + 0);
    float4 rb1 = *(const float4*)(Bp + 4);

    for (int kb = 0; kb < 256; kb += 16) {
        __syncthreads();
        As[lk8 + 0][lr] = ra0.x; As[lk8 + 1][lr] = ra0.y; As[lk8 + 2][lr] = ra0.z; As[lk8 + 3][lr] = ra0.w;
        As[lk8 + 4][lr] = ra1.x; As[lk8 + 5][lr] = ra1.y; As[lk8 + 6][lr] = ra1.z; As[lk8 + 7][lr] = ra1.w;
        Bs[lk8 + 0][lr] = rb0.x; Bs[lk8 + 1][lr] = rb0.y; Bs[lk8 + 2][lr] = rb0.z; Bs[lk8 + 3][lr] = rb0.w;
        Bs[lk8 + 4][lr] = rb1.x; Bs[lk8 + 5][lr] = rb1.y; Bs[lk8 + 6][lr] = rb1.z; Bs[lk8 + 7][lr] = rb1.w;
        __syncthreads();
        if (kb < 240) {
            ra0 = *(const float4*)(Ap + kb + 16);
            ra1 = *(const float4*)(Ap + kb + 20);
            rb0 = *(const float4*)(Bp + kb + 16);
            rb1 = *(const float4*)(Bp + kb + 20);
        }
#pragma unroll
        for (int kk = 0; kk < 16; kk++) {
            float4 av0 = *(const float4*)&As[kk][ty * 8];
            float4 av1 = *(const float4*)&As[kk][ty * 8 + 4];
            float4 bv0 = *(const float4*)&Bs[kk][tx * 8];
            float4 bv1 = *(const float4*)&Bs[kk][tx * 8 + 4];
            float a[8] = {av0.x, av0.y, av0.z, av0.w, av1.x, av1.y, av1.z, av1.w};
            float b[8] = {bv0.x, bv0.y, bv0.z, bv0.w, bv1.x, bv1.y, bv1.z, bv1.w};
#pragma unroll
            for (int i = 0; i < 8; i++)
#pragma unroll
                for (int j = 0; j < 8; j++)
                    acc[i][j] += a[i] * b[j];
        }
    }

    float4 bb0 = *(const float4*)(bias + bn + tx * 8);
    float4 bb1 = *(const float4*)(bias + bn + tx * 8 + 4);
    float bbv[8] = {bb0.x, bb0.y, bb0.z, bb0.w, bb1.x, bb1.y, bb1.z, bb1.w};

#pragma unroll
    for (int i = 0; i < 8; i++) {
        int row = bm + ty * 8 + i;
        float o[8];
#pragma unroll
        for (int j = 0; j < 8; j++) o[j] = acc[i][j] + bbv[j];
        float4 o0 = {o[0], o[1], o[2], o[3]};
        float4 o1 = {o[4], o[5], o[6], o[7]};
        float* cp = C + (size_t)row * N + bn + tx * 8;
        *(float4*)(cp)     = o0;
        *(float4*)(cp + 4) = o1;
        if (do_lse) {
            // logits bounded by ~16.1 -> max-free sum-exp is safe in fp32
            float s = 0.f;
#pragma unroll
            for (int j = 0; j < 8; j++) s += __expf(o[j]);
            s += __shfl_xor_sync(0xffffffffu, s, 1);
            s += __shfl_xor_sync(0xffffffffu, s, 2);
            s += __shfl_xor_sync(0xffffffffu, s, 4);
            s += __shfl_xor_sync(0xffffffffu, s, 8);
            if (tx == 0) atomicAdd(&g_sumexp[row], s);
        }
    }
}

// ---------------------------------------------------------------------------
// 3) Sequential GRU scan, single 8-CTA cluster.
//    CTA c owns hidden units [32c, 32c+32) and 96 rows of each W_hh in SMEM.
//    Sync: two mbarriers (ping/pong per half-step slot), 256 arrivals each
//    (32 producer lanes x 8 source CTAs). Each lane's release-arrive seals its
//    own st.shared::cluster h-broadcasts; consumers acquire on the local
//    barrier. NO barrier.cluster in the loop -> no per-step CCTL.IVALL flush.
//    Phase safety: a source re-arrives on bar[p] only after passing its wait
//    on bar[p^1], which requires every CTA consumed bar[p]'s previous phase.
// ---------------------------------------------------------------------------
__device__ __forceinline__ void half_step(
    const float* __restrict__ W, float* hb, float* ghbuf,
    int p, int tid, int unit,
    float g_r, float g_z, float g_n,
    float b_r, float b_z, float b_n,
    bool write_hs, int t,
    const uint32_t* h_rem, const uint32_t* bar_rem,
    uint32_t bar_loc, uint32_t parity)
{
    int rt = tid >> 2;             // row team 0..95  (g*32 + j)
    int m  = tid & 3;              // lane within team
    const float* Wrow = W + rt * WPITCH;
    const float* hp   = hb + p * H;

    float a0 = 0.f, a1 = 0.f, a2 = 0.f, a3 = 0.f;
#pragma unroll
    for (int it = 0; it < 16; it++) {
        int ch = (it * 4 + m) * 4;                     // float offset, 16B chunks
        float4 w  = *(const float4*)(Wrow + ch);
        float4 hv = *(const float4*)(hp + ch);
        a0 += w.x * hv.x; a1 += w.y * hv.y; a2 += w.z * hv.z; a3 += w.w * hv.w;
    }
    float acc = (a0 + a1) + (a2 + a3);
    acc += __shfl_xor_sync(0xffffffffu, acc, 1);
    acc += __shfl_xor_sync(0xffffffffu, acc, 2);
    if (m == 0) ghbuf[rt] = acc;
    __syncthreads();

    if (tid < SLICE) {
        float r = 1.f / (1.f + expf(-(g_r + ghbuf[tid]      + b_r)));
        float z = 1.f / (1.f + expf(-(g_z + ghbuf[32 + tid] + b_z)));
        float n = tanhf(g_n + r * (ghbuf[64 + tid] + b_n));
        float hold = hp[unit];
        float hnew = (1.f - z) * n + z * hold;
        if (write_hs) g_Hs[t * H + unit] = hnew;
        // broadcast new h[unit] to every CTA's (p^1) buffer (incl. self)
#pragma unroll
        for (int d = 0; d < CLN; d++)
            asm volatile("st.shared::cluster.f32 [%0], %1;"
                         :: "r"(h_rem[d]), "f"(hnew) : "memory");
        // seal with release-arrives (this thread's stores ordered before each)
#pragma unroll
        for (int d = 0; d < CLN; d++)
            mbar_arrive_cluster(bar_rem[d]);
    }
    mbar_wait_cluster(bar_loc, parity);   // acquire: peers' h(p^1) now visible
}

__global__ void __cluster_dims__(CLN, 1, 1) __launch_bounds__(SCAN_THREADS, 1)
scan_kernel(const float* __restrict__ eWhh, const float* __restrict__ eBhh,
            const float* __restrict__ dWhh, const float* __restrict__ dBhh)
{
    extern __shared__ float sm[];
    unsigned long long* bars = (unsigned long long*)sm;  // 2 mbarriers (16B)
    float* We    = sm + 4;                               // 96 * 272
    float* Wd    = We + ROWS_PER_CTA * WPITCH;           // 96 * 272
    float* hb    = Wd + ROWS_PER_CTA * WPITCH;           // 2 * 256 (double buffer)
    float* ghbuf = hb + 2 * H;                           // 96

    int tid = threadIdx.x;
    int c = blockIdx.x;                                  // slice owner id

    // Load this CTA's 96 rows of each W_hh into padded SMEM
    for (int idx = tid; idx < ROWS_PER_CTA * 64; idx += SCAN_THREADS) {
        int lr = idx >> 6;
        int q  = (idx & 63) * 4;
        int g  = lr >> 5;
        int j  = lr & 31;
        size_t off = (size_t)(g * H + c * SLICE + j) * H + q;
        *(float4*)(We + lr * WPITCH + q) = *(const float4*)(eWhh + off);
        *(float4*)(Wd + lr * WPITCH + q) = *(const float4*)(dWhh + off);
    }
    for (int i = tid; i < 2 * H; i += SCAN_THREADS) hb[i] = 0.f;

    int unit = c * SLICE + tid;                          // valid when tid < 32
    float be_r = 0.f, be_z = 0.f, be_n = 0.f, bd_r = 0.f, bd_z = 0.f, bd_n = 0.f;
    if (tid < SLICE) {
        be_r = eBhh[unit]; be_z = eBhh[H + unit]; be_n = eBhh[2 * H + unit];
        bd_r = dBhh[unit]; bd_z = dBhh[H + unit]; bd_n = dBhh[2 * H + unit];
    }

    uint32_t bl0 = cvta_smem(&bars[0]);
    uint32_t bl1 = cvta_smem(&bars[1]);
    if (tid == 0) {
        mbar_init(bl0, CLN * SLICE);   // 256 arrivals per phase
        mbar_init(bl1, CLN * SLICE);
    }

    // precompute remote store / arrive addresses (loop-invariant)
    uint32_t hr[2][CLN], br[2][CLN];
    {
        int us = c * SLICE + (tid & (SLICE - 1));        // in-range for all tids
        uint32_t lh1 = cvta_smem(hb + H + us);           // dest buffer when p=0
        uint32_t lh0 = cvta_smem(hb + us);               // dest buffer when p=1
#pragma unroll
        for (int d = 0; d < CLN; d++) {
            hr[0][d] = mapa_u32(lh1, d);
            hr[1][d] = mapa_u32(lh0, d);
            br[0][d] = mapa_u32(bl0, d);
            br[1][d] = mapa_u32(bl1, d);
        }
    }

    CLUSTER_SYNC_();   // buffers + mbarriers initialized before any peer access

    for (int t = 0; t < T_SEQ; t++) {
        uint32_t par = (uint32_t)(t & 1);
        // prefetch precomputed gi for this step (hidden under matvec latency)
        float ge_r = 0.f, ge_z = 0.f, ge_n = 0.f, gd_r = 0.f, gd_z = 0.f, gd_n = 0.f;
        if (tid < SLICE) {
            const float* gie = g_gi_enc + t * G3 + unit;
            ge_r = gie[0]; ge_z = gie[H]; ge_n = gie[2 * H];
            const float* gid = g_gi_dec + t * G3 + unit;
            gd_r = gid[0]; gd_z = gid[H]; gd_n = gid[2 * H];
        }
        // encoder: read h(0) -> write h(1), sealed by bar0
        half_step(We, hb, ghbuf, 0, tid, unit, ge_r, ge_z, ge_n, be_r, be_z, be_n,
                  false, t, hr[0], br[0], bl0, par);
        // decoder: read h(1) -> write h(0), sealed by bar1; record h into g_Hs
        half_step(Wd, hb, ghbuf, 1, tid, unit, gd_r, gd_z, gd_n, bd_r, bd_z, bd_n,
                  true, t, hr[1], br[1], bl1, par);
    }

    CLUSTER_SYNC_();   // no CTA exits while peers could still touch its SMEM
}

// ---------------------------------------------------------------------------
// 4) log-softmax fix-up: out[t][v] = logit - log(sumexp[t])
// ---------------------------------------------------------------------------
__global__ void finalize_kernel(float* __restrict__ out)
{
    int i = blockIdx.x * blockDim.x + threadIdx.x;
    int total4 = T_SEQ * (VOUT / 4);
    int stride = gridDim.x * blockDim.x;
    float4* o4 = (float4*)out;
    for (; i < total4; i += stride) {
        int row = i / (VOUT / 4);
        float l = logf(g_sumexp[row]);
        float4 v = o4[i];
        v.x -= l; v.y -= l; v.z -= l; v.w -= l;
        o4[i] = v;
    }
}

// ---------------------------------------------------------------------------
// Launch (graph-capturable: kernel launches only on the default stream)
// ---------------------------------------------------------------------------
extern "C" void kernel_launch(void* const* d_in, const int* in_sizes, int n_in,
                              void* d_out, int out_size)
{
    const int*   src      = (const int*)  d_in[0];
    const int*   trg      = (const int*)  d_in[1];
    const float* enc_emb  = (const float*)d_in[2];
    const float* enc_W_ih = (const float*)d_in[3];
    const float* enc_W_hh = (const float*)d_in[4];
    const float* enc_b_ih = (const float*)d_in[5];
    const float* enc_b_hh = (const float*)d_in[6];
    const float* dec_emb  = (const float*)d_in[7];
    const float* dec_W_ih = (const float*)d_in[8];
    const float* dec_W_hh = (const float*)d_in[9];
    const float* dec_b_ih = (const float*)d_in[10];
    const float* dec_b_hh = (const float*)d_in[11];
    const float* out_W    = (const float*)d_in[12];
    const float* out_b    = (const float*)d_in[13];
    float* out = (float*)d_out;

    float *pXe, *pXd, *pGe, *pGd, *pHs;
    cudaGetSymbolAddress((void**)&pXe, g_Xenc);
    cudaGetSymbolAddress((void**)&pXd, g_Xdec);
    cudaGetSymbolAddress((void**)&pGe, g_gi_enc);
    cudaGetSymbolAddress((void**)&pGd, g_gi_dec);
    cudaGetSymbolAddress((void**)&pHs, g_Hs);

    const int scan_smem = (4 + 2 * ROWS_PER_CTA * WPITCH + 2 * H + ROWS_PER_CTA)
                          * (int)sizeof(float);
    cudaFuncSetAttribute(scan_kernel, cudaFuncAttributeMaxDynamicSharedMemorySize, scan_smem);

    // 1) gather x vectors (+ relu) and zero sum-exp accumulators
    gather_kernel<<<T_SEQ, 256>>>(src, trg, enc_emb, dec_emb);

    // 2) precompute input-side gate pre-activations (parallel over all t)
    gemm_kernel<<<dim3(T_SEQ / 128, G3 / 128), 256>>>(pXe, enc_W_ih, enc_b_ih, pGe, G3, 0);
    gemm_kernel<<<dim3(T_SEQ / 128, G3 / 128), 256>>>(pXd, dec_W_ih, dec_b_ih, pGd, G3, 0);

    // 3) sequential GRU scan (one 8-CTA cluster, weights SMEM-resident)
    scan_kernel<<<CLN, SCAN_THREADS, scan_smem>>>(enc_W_hh, enc_b_hh, dec_W_hh, dec_b_hh);

    // 4) output projection + per-row sum-exp epilogue
    gemm_kernel<<<dim3(T_SEQ / 128, VOUT / 128), 256>>>(pHs, out_W, out_b, out, VOUT, 1);

    // 5) log-softmax fix-up
    finalize_kernel<<<2048, 256>>>(out);
}

// round 9
// speedup vs baseline: 3.0850x; 3.0850x over previous
#include <cuda_runtime.h>
#include <cstdint>
#include <math.h>

// Problem constants
#define T_SEQ 2048
#define H     256
#define G3    768          // 3*H gate rows
#define VOUT  32000

// Scan cluster config
#define CLN          8     // cluster size
#define SLICE        32    // hidden units per CTA (H / CLN)
#define SCAN_THREADS 384   // 12 warps * 32; warp w computes rows [8w, 8w+8)

// ---------------------------------------------------------------------------
// Device scratch (static __device__ arrays: allocation-free per harness rules)
// ---------------------------------------------------------------------------
__device__ __align__(16) float g_Xenc[T_SEQ * H];
__device__ __align__(16) float g_Xdec[T_SEQ * H];
__device__ __align__(16) float g_gi_enc[T_SEQ * G3];
__device__ __align__(16) float g_gi_dec[T_SEQ * G3];
__device__ __align__(16) float g_Hs[T_SEQ * H];
__device__ __align__(16) float g_sumexp[T_SEQ];

// ---------------------------------------------------------------------------
// PTX helpers
// ---------------------------------------------------------------------------
__device__ __forceinline__ uint32_t cvta_smem(const void* p) {
    return (uint32_t)__cvta_generic_to_shared(p);
}
__device__ __forceinline__ uint32_t mapa_u32(uint32_t laddr, uint32_t rank) {
    uint32_t r;
    asm("mapa.shared::cluster.u32 %0, %1, %2;" : "=r"(r) : "r"(laddr), "r"(rank));
    return r;
}
#define CLUSTER_SYNC_() do { \
    asm volatile("barrier.cluster.arrive.aligned;" ::: "memory"); \
    asm volatile("barrier.cluster.wait.aligned;"   ::: "memory"); \
} while (0)

// ---------------------------------------------------------------------------
// 1) Gather embeddings (+ relu for decoder input) and zero the sum-exp accum.
// ---------------------------------------------------------------------------
__global__ void gather_kernel(const int* __restrict__ src, const int* __restrict__ trg,
                              const float* __restrict__ enc_emb,
                              const float* __restrict__ dec_emb)
{
    int t = blockIdx.x;
    int i = threadIdx.x;           // 256 threads
    int s = src[t];
    int d = trg[t];
    g_Xenc[t * H + i] = enc_emb[(size_t)s * H + i];
    float v = dec_emb[(size_t)d * H + i];
    g_Xdec[t * H + i] = v > 0.f ? v : 0.f;
    if (t < T_SEQ / H) g_sumexp[t * H + i] = 0.f;   // 8 blocks zero all 2048 entries
}

// ---------------------------------------------------------------------------
// 2) fp32 GEMM: C[M][N] = A[M][256] * B[N][256]^T + bias[N]
//    128x128 tiles, BK=16, 256 threads, 8x8 micro-tile.
//    do_lse: accumulate per-row sum(exp(c)) into g_sumexp (logits GEMM only).
// ---------------------------------------------------------------------------
__global__ __launch_bounds__(256)
void gemm_kernel(const float* __restrict__ A, const float* __restrict__ B,
                 const float* __restrict__ bias, float* __restrict__ C,
                 int N, int do_lse)
{
    __shared__ float As[16][132];   // [k][m], padded
    __shared__ float Bs[16][132];   // [k][n], padded

    int tid = threadIdx.x;
    int tx = tid & 15;              // 0..15 : col group (8 cols)
    int ty = tid >> 4;              // 0..15 : row group (8 rows)
    int bm = blockIdx.x * 128;
    int bn = blockIdx.y * 128;

    int lr  = tid >> 1;             // 0..127 : tile row for loads
    int lk8 = (tid & 1) * 8;        // 0 or 8 : k offset for loads

    const float* Ap = A + (size_t)(bm + lr) * 256 + lk8;
    const float* Bp = B + (size_t)(bn + lr) * 256 + lk8;

    float acc[8][8] = {};

    float4 ra0 = *(const float4*)(Ap + 0);
    float4 ra1 = *(const float4*)(Ap + 4);
    float4 rb0 = *(const float4*)(Bp + 0);
    float4 rb1 = *(const float4*)(Bp + 4);

    for (int kb = 0; kb < 256; kb += 16) {
        __syncthreads();
        As[lk8 + 0][lr] = ra0.x; As[lk8 + 1][lr] = ra0.y; As[lk8 + 2][lr] = ra0.z; As[lk8 + 3][lr] = ra0.w;
        As[lk8 + 4][lr] = ra1.x; As[lk8 + 5][lr] = ra1.y; As[lk8 + 6][lr] = ra1.z; As[lk8 + 7][lr] = ra1.w;
        Bs[lk8 + 0][lr] = rb0.x; Bs[lk8 + 1][lr] = rb0.y; Bs[lk8 + 2][lr] = rb0.z; Bs[lk8 + 3][lr] = rb0.w;
        Bs[lk8 + 4][lr] = rb1.x; Bs[lk8 + 5][lr] = rb1.y; Bs[lk8 + 6][lr] = rb1.z; Bs[lk8 + 7][lr] = rb1.w;
        __syncthreads();
        if (kb < 240) {
            ra0 = *(const float4*)(Ap + kb + 16);
            ra1 = *(const float4*)(Ap + kb + 20);
            rb0 = *(const float4*)(Bp + kb + 16);
            rb1 = *(const float4*)(Bp + kb + 20);
        }
#pragma unroll
        for (int kk = 0; kk < 16; kk++) {
            float4 av0 = *(const float4*)&As[kk][ty * 8];
            float4 av1 = *(const float4*)&As[kk][ty * 8 + 4];
            float4 bv0 = *(const float4*)&Bs[kk][tx * 8];
            float4 bv1 = *(const float4*)&Bs[kk][tx * 8 + 4];
            float a[8] = {av0.x, av0.y, av0.z, av0.w, av1.x, av1.y, av1.z, av1.w};
            float b[8] = {bv0.x, bv0.y, bv0.z, bv0.w, bv1.x, bv1.y, bv1.z, bv1.w};
#pragma unroll
            for (int i = 0; i < 8; i++)
#pragma unroll
                for (int j = 0; j < 8; j++)
                    acc[i][j] += a[i] * b[j];
        }
    }

    float4 bb0 = *(const float4*)(bias + bn + tx * 8);
    float4 bb1 = *(const float4*)(bias + bn + tx * 8 + 4);
    float bbv[8] = {bb0.x, bb0.y, bb0.z, bb0.w, bb1.x, bb1.y, bb1.z, bb1.w};

#pragma unroll
    for (int i = 0; i < 8; i++) {
        int row = bm + ty * 8 + i;
        float o[8];
#pragma unroll
        for (int j = 0; j < 8; j++) o[j] = acc[i][j] + bbv[j];
        float4 o0 = {o[0], o[1], o[2], o[3]};
        float4 o1 = {o[4], o[5], o[6], o[7]};
        float* cp = C + (size_t)row * N + bn + tx * 8;
        *(float4*)(cp)     = o0;
        *(float4*)(cp + 4) = o1;
        if (do_lse) {
            // logits bounded by ~16.1 -> max-free sum-exp is safe in fp32
            float s = 0.f;
#pragma unroll
            for (int j = 0; j < 8; j++) s += __expf(o[j]);
            s += __shfl_xor_sync(0xffffffffu, s, 1);
            s += __shfl_xor_sync(0xffffffffu, s, 2);
            s += __shfl_xor_sync(0xffffffffu, s, 4);
            s += __shfl_xor_sync(0xffffffffu, s, 8);
            if (tx == 0) atomicAdd(&g_sumexp[row], s);
        }
    }
}

// ---------------------------------------------------------------------------
// 3) Sequential GRU scan, single 8-CTA cluster, WEIGHTS IN REGISTERS.
//    CTA c owns hidden units [32c, 32c+32) -> 96 rows of each W_hh.
//    12 warps; warp w computes rows [8w, 8w+8). Lane l holds the 8x8 weight
//    patch w[8w+i][8l..8l+8) for BOTH matrices (128 regs) and h[8l..8l+8)
//    (2 LDS.128/half-step). Row sums via butterfly shuffles.
//    Sync: barrier.cluster (one per half-step) -- the R6-proven protocol.
// ---------------------------------------------------------------------------
__shared__ float sh_hb[2 * H];        // replicated h, double buffered
__shared__ float sh_gh[96];           // row sums (r/z/n x 32 units)
__shared__ float sh_bias[192];        // [0:96) enc b_hh gates, [96:192) dec
__shared__ uint32_t sh_pbase[2][CLN]; // remote dest-buffer base addrs

__device__ __forceinline__ void half_step_reg(
    const float (&wgt)[8][8], int p, int tid, int l, int w, int k, int unit,
    float g_r, float g_z, float g_n, int bias_off,
    bool write_hs, int t)
{
    // h slice (broadcast LDS across warps)
    float4 h0 = *(const float4*)&sh_hb[p * H + 8 * l];
    float4 h1 = *(const float4*)&sh_hb[p * H + 8 * l + 4];
    float hh[8] = {h0.x, h0.y, h0.z, h0.w, h1.x, h1.y, h1.z, h1.w};

    float acc[8];
#pragma unroll
    for (int i = 0; i < 8; i++) {
        float a = 0.f;
#pragma unroll
        for (int j = 0; j < 8; j++) a += wgt[i][j] * hh[j];
        acc[i] = a;
    }
    // butterfly within 8-lane groups
#pragma unroll
    for (int s = 1; s <= 4; s <<= 1)
#pragma unroll
        for (int i = 0; i < 8; i++)
            acc[i] += __shfl_xor_sync(0xffffffffu, acc[i], s);
    // transpose: lane picks its row-class value (static unroll -> SEL chain)
    float v = acc[0];
#pragma unroll
    for (int i = 1; i < 8; i++) v = (k == i) ? acc[i] : v;
    // combine the 4 groups
    v += __shfl_xor_sync(0xffffffffu, v, 8);
    v += __shfl_xor_sync(0xffffffffu, v, 16);
    if (l < 8) sh_gh[8 * w + l] = v;
    __syncthreads();

    if (tid < SLICE) {
        float r = 1.f / (1.f + expf(-(g_r + sh_gh[tid]      + sh_bias[bias_off + tid])));
        float z = 1.f / (1.f + expf(-(g_z + sh_gh[32 + tid] + sh_bias[bias_off + 32 + tid])));
        float n = tanhf(g_n + r * (sh_gh[64 + tid] + sh_bias[bias_off + 64 + tid]));
        float hold = sh_hb[p * H + unit];
        float hnew = (1.f - z) * n + z * hold;
        if (write_hs) g_Hs[t * H + unit] = hnew;
        uint32_t off = 4u * (uint32_t)unit;
#pragma unroll
        for (int d = 0; d < CLN; d++)
            asm volatile("st.shared::cluster.f32 [%0], %1;"
                         :: "r"(sh_pbase[p][d] + off), "f"(hnew) : "memory");
    }
    CLUSTER_SYNC_();  // release own stores / acquire peers'
}

__global__ void __cluster_dims__(CLN, 1, 1) __launch_bounds__(SCAN_THREADS, 1)
scan_kernel(const float* __restrict__ eWhh, const float* __restrict__ eBhh,
            const float* __restrict__ dWhh, const float* __restrict__ dBhh)
{
    int tid = threadIdx.x;
    int l = tid & 31;
    int w = tid >> 5;                 // warp 0..11
    int k = l & 7;                    // row class within warp
    int c = blockIdx.x;               // slice owner id
    int unit = c * SLICE + tid;       // valid when tid < 32

    // ---- load this thread's weight patches into registers ----
    float wE[8][8], wD[8][8];
#pragma unroll
    for (int i = 0; i < 8; i++) {
        int row = 8 * w + i;          // 0..95
        int g = row >> 5;
        int j = row & 31;
        size_t off = (size_t)(g * H + c * SLICE + j) * H + 8 * l;
        float4 e0 = *(const float4*)(eWhh + off);
        float4 e1 = *(const float4*)(eWhh + off + 4);
        float4 d0 = *(const float4*)(dWhh + off);
        float4 d1 = *(const float4*)(dWhh + off + 4);
        wE[i][0] = e0.x; wE[i][1] = e0.y; wE[i][2] = e0.z; wE[i][3] = e0.w;
        wE[i][4] = e1.x; wE[i][5] = e1.y; wE[i][6] = e1.z; wE[i][7] = e1.w;
        wD[i][0] = d0.x; wD[i][1] = d0.y; wD[i][2] = d0.z; wD[i][3] = d0.w;
        wD[i][4] = d1.x; wD[i][5] = d1.y; wD[i][6] = d1.z; wD[i][7] = d1.w;
    }

    // ---- init shared state ----
    if (tid < 2 * H) sh_hb[tid] = 0.f;
    if (tid < 96)  sh_bias[tid]      = eBhh[(tid >> 5) * H + c * SLICE + (tid & 31)];
    else if (tid < 192) {
        int q = tid - 96;
        sh_bias[tid] = dBhh[(q >> 5) * H + c * SLICE + (q & 31)];
    }
    if (tid < CLN) {
        sh_pbase[0][tid] = mapa_u32(cvta_smem(&sh_hb[H]), tid);  // dest when p=0
        sh_pbase[1][tid] = mapa_u32(cvta_smem(&sh_hb[0]), tid);  // dest when p=1
    }

    CLUSTER_SYNC_();  // buffers initialized before any peer DSMEM write

    for (int t = 0; t < T_SEQ; t++) {
        float ge_r = 0.f, ge_z = 0.f, ge_n = 0.f, gd_r = 0.f, gd_z = 0.f, gd_n = 0.f;
        if (tid < SLICE) {
            const float* gie = g_gi_enc + t * G3 + unit;
            ge_r = gie[0]; ge_z = gie[H]; ge_n = gie[2 * H];
            const float* gid = g_gi_dec + t * G3 + unit;
            gd_r = gid[0]; gd_z = gid[H]; gd_n = gid[2 * H];
        }
        // encoder: read h(0) -> write h(1)
        half_step_reg(wE, 0, tid, l, w, k, unit, ge_r, ge_z, ge_n, 0,   false, t);
        // decoder: read h(1) -> write h(0); record h into g_Hs
        half_step_reg(wD, 1, tid, l, w, k, unit, gd_r, gd_z, gd_n, 96,  true,  t);
    }

    CLUSTER_SYNC_();  // no CTA exits while peers could still touch its SMEM
}

// ---------------------------------------------------------------------------
// 4) log-softmax fix-up: out[t][v] = logit - log(sumexp[t])
//    grid (32, T_SEQ): block y = row -> no per-element division.
// ---------------------------------------------------------------------------
__global__ void finalize_kernel(float* __restrict__ out)
{
    int row = blockIdx.y;
    int i = blockIdx.x * blockDim.x + threadIdx.x;     // float4 index in row
    if (i >= VOUT / 4) return;
    float lg = logf(g_sumexp[row]);
    float4* o4 = (float4*)(out + (size_t)row * VOUT) + i;
    float4 v = *o4;
    v.x -= lg; v.y -= lg; v.z -= lg; v.w -= lg;
    *o4 = v;
}

// ---------------------------------------------------------------------------
// Launch (graph-capturable: kernel launches only on the default stream)
// ---------------------------------------------------------------------------
extern "C" void kernel_launch(void* const* d_in, const int* in_sizes, int n_in,
                              void* d_out, int out_size)
{
    const int*   src      = (const int*)  d_in[0];
    const int*   trg      = (const int*)  d_in[1];
    const float* enc_emb  = (const float*)d_in[2];
    const float* enc_W_ih = (const float*)d_in[3];
    const float* enc_W_hh = (const float*)d_in[4];
    const float* enc_b_ih = (const float*)d_in[5];
    const float* enc_b_hh = (const float*)d_in[6];
    const float* dec_emb  = (const float*)d_in[7];
    const float* dec_W_ih = (const float*)d_in[8];
    const float* dec_W_hh = (const float*)d_in[9];
    const float* dec_b_ih = (const float*)d_in[10];
    const float* dec_b_hh = (const float*)d_in[11];
    const float* out_W    = (const float*)d_in[12];
    const float* out_b    = (const float*)d_in[13];
    float* out = (float*)d_out;

    float *pXe, *pXd, *pGe, *pGd, *pHs;
    cudaGetSymbolAddress((void**)&pXe, g_Xenc);
    cudaGetSymbolAddress((void**)&pXd, g_Xdec);
    cudaGetSymbolAddress((void**)&pGe, g_gi_enc);
    cudaGetSymbolAddress((void**)&pGd, g_gi_dec);
    cudaGetSymbolAddress((void**)&pHs, g_Hs);

    // 1) gather x vectors (+ relu) and zero sum-exp accumulators
    gather_kernel<<<T_SEQ, 256>>>(src, trg, enc_emb, dec_emb);

    // 2) precompute input-side gate pre-activations (parallel over all t)
    gemm_kernel<<<dim3(T_SEQ / 128, G3 / 128), 256>>>(pXe, enc_W_ih, enc_b_ih, pGe, G3, 0);
    gemm_kernel<<<dim3(T_SEQ / 128, G3 / 128), 256>>>(pXd, dec_W_ih, dec_b_ih, pGd, G3, 0);

    // 3) sequential GRU scan (one 8-CTA cluster, weights register-resident)
    scan_kernel<<<CLN, SCAN_THREADS>>>(enc_W_hh, enc_b_hh, dec_W_hh, dec_b_hh);

    // 4) output projection + per-row sum-exp epilogue
    gemm_kernel<<<dim3(T_SEQ / 128, VOUT / 128), 256>>>(pHs, out_W, out_b, out, VOUT, 1);

    // 5) log-softmax fix-up
    finalize_kernel<<<dim3((VOUT / 4 + 255) / 256, T_SEQ), 256>>>(out);
}